// round 11
// baseline (speedup 1.0000x reference)
#include <cuda_runtime.h>
#include <cuda_fp16.h>
#include <cstdint>

// Problem constants
#define NLAT 181
#define NLON 360
#define CIN  128
#define COUT 128
#define KS   3
#define BSZ  2
#define CHW  (NLAT * NLON)     // 65160
#define CK   (CIN * KS)        // 384
#define PT   32                // gather p-tile
#define NPT  12
#define MTOT  (BSZ * CHW)      // 130320
#define MTILE 128
#define MBLK  ((MTOT + MTILE - 1) / MTILE)   // 1019
#define MPADL (MBLK * MTILE)                 // 130432
#define WSLOT 4096
#define RSLOT 512
#define XPAD  368              // padded x row (8 duplicate cols kill per-col wraps)
#define KCH   32               // GEMM K-chunk (halves)
#define NCH   (CK / KCH)       // 12
#define SROWB 112              // smem row stride bytes
#define CHNKB (128 * SROWB)
#define STGB  (2 * CHNKB)
#define NSTG  3

// Scratch (device globals — allocation-free; zero-init so padded z rows are 0)
__device__ float  g_xt[(size_t)BSZ * NLAT * XPAD * CIN];  // x: [b][la][col<368][c]
__device__ float  g_rwp[(size_t)NLAT * WSLOT * 6];        // {w0,w0,w1,w1,w2,w2} per entry
__device__ int4   g_runs[NLAT * RSLOT];                   // {la, lo0, cnt_padded, wabs}
__device__ int    g_rcnt[NLAT];
__device__ __half g_zh[(size_t)MPADL * CK];               // z M-major [m][ck], fp16
__device__ __half g_wh[COUT * CK];                        // W [f][ck], fp16

// ---------------- helpers ----------------
__device__ __forceinline__ void fma2(unsigned long long& d,
                                     unsigned long long a,
                                     unsigned long long b) {
    asm("fma.rn.f32x2 %0, %1, %2, %0;" : "+l"(d) : "l"(a), "l"(b));
}
union F4U { float4 f; unsigned long long u[2]; };
union U2F { unsigned long long u; float2 f; };

__device__ __forceinline__ uint32_t smem_u32(const void* p) {
    uint32_t a;
    asm("{ .reg .u64 t; cvta.to.shared.u64 t, %1; cvt.u32.u64 %0, t; }"
        : "=r"(a) : "l"(p));
    return a;
}
__device__ __forceinline__ void cpasync16(uint32_t s, const void* g) {
    asm volatile("cp.async.cg.shared.global [%0], [%1], 16;" :: "r"(s), "l"(g));
}
__device__ __forceinline__ void cp_commit() {
    asm volatile("cp.async.commit_group;" ::: "memory");
}
template <int N>
__device__ __forceinline__ void cp_wait() {
    asm volatile("cp.async.wait_group %0;" :: "n"(N) : "memory");
}
__device__ __forceinline__ void mma_f16(float* d, const uint32_t* a,
                                        uint32_t b0, uint32_t b1) {
    asm volatile(
        "mma.sync.aligned.m16n8k16.row.col.f32.f16.f16.f32 "
        "{%0,%1,%2,%3}, {%4,%5,%6,%7}, {%8,%9}, {%0,%1,%2,%3};"
        : "+f"(d[0]), "+f"(d[1]), "+f"(d[2]), "+f"(d[3])
        : "r"(a[0]), "r"(a[1]), "r"(a[2]), "r"(a[3]), "r"(b0), "r"(b1));
}
__device__ __forceinline__ void ldsm_x4(uint32_t& r0, uint32_t& r1,
                                        uint32_t& r2, uint32_t& r3, uint32_t addr) {
    asm volatile("ldmatrix.sync.aligned.m8n8.x4.shared.b16 {%0,%1,%2,%3}, [%4];"
                 : "=r"(r0), "=r"(r1), "=r"(r2), "=r"(r3) : "r"(addr));
}

// ---------------------------------------------------------------------------
// Transpose x[b][c][hw] -> g_xt[b][la][col][c], padded rows (dup cols 0..7).
// ---------------------------------------------------------------------------
__global__ void transpose_kernel(const float* __restrict__ x) {
    __shared__ float tile[32][33];
    const int hw0 = blockIdx.x * 32;
    const int c0  = blockIdx.y * 32;
    const int b   = blockIdx.z;
    const int tx = threadIdx.x, ty = threadIdx.y;
    #pragma unroll
    for (int i = 0; i < 4; i++) {
        int c  = c0 + ty + i * 8;
        int hw = hw0 + tx;
        if (hw < CHW)
            tile[ty + i * 8][tx] = x[((size_t)b * CIN + c) * CHW + hw];
    }
    __syncthreads();
    #pragma unroll
    for (int i = 0; i < 4; i++) {
        int hw = hw0 + ty + i * 8;
        int c  = c0 + tx;
        if (hw < CHW) {
            const int la = hw / NLON;
            const int lo = hw - la * NLON;
            const float v = tile[tx][ty + i * 8];
            float* rowp = g_xt + ((size_t)(b * NLAT + la) * XPAD) * CIN + c;
            rowp[(size_t)lo * CIN] = v;
            if (lo < XPAD - NLON) rowp[(size_t)(lo + NLON) * CIN] = v;
        }
    }
}

// W[f][ck] -> fp16 copy
__global__ void wconv_kernel(const float* __restrict__ w) {
    int i = blockIdx.x * 256 + threadIdx.x;
    if (i < COUT * CK) g_wh[i] = __float2half_rn(w[i]);
}

// ---------------------------------------------------------------------------
// Merge: warp per t. Emits per-(t,la) runs of consecutive lons. Each entry is
// stored as 6 floats {w0,w0,w1,w1,w2,w2} (pre-duplicated f32x2 multiplicands),
// runs zero-padded to multiples of 4 entries.
// ---------------------------------------------------------------------------
__global__ void merge_kernel(const int* __restrict__ seg,
                             const int* __restrict__ lat,
                             const int* __restrict__ lon,
                             const float* __restrict__ vals,
                             const float* __restrict__ qw,
                             int nnz) {
    const int t    = (blockIdx.x * blockDim.x + threadIdx.x) >> 5;
    const int lane = threadIdx.x & 31;
    if (t >= NLAT) return;

    int sb[4];
    #pragma unroll
    for (int k = 0; k < 4; k++) {
        const int j = t * KS + k;
        int lo = 0, hi = nnz;
        while (lo < hi) {
            int m = (lo + hi) >> 1;
            int sgv = seg[m];
            int key = (sgv % NLAT) * KS + (sgv / NLAT);
            if (key < j) lo = m + 1; else hi = m;
        }
        sb[k] = lo;
    }

    const int wlim = (t + 1) * WSLOT;
    int wabs = 0, rbase = 0;
    int entc = 0, runsc = 0;

    #define EMIT_ENTRY(AI, W0, W1, W2)                                   \
    if ((AI) < wlim) {                                                   \
        float* wpp = g_rwp + (size_t)(AI) * 6;                           \
        wpp[0] = (W0); wpp[1] = (W0); wpp[2] = (W1);                     \
        wpp[3] = (W1); wpp[4] = (W2); wpp[5] = (W2);                     \
    }

    for (int pass = 0; pass < 2; pass++) {
        int ent = 0, runs = 0;
        for (int la = lane; la < NLAT; la += 32) {
            int bks[3], eks[3];
            #pragma unroll
            for (int k = 0; k < 3; k++) {
                int lo = sb[k], hi = sb[k + 1];
                while (lo < hi) { int m = (lo + hi) >> 1; if (lat[m] < la) lo = m + 1; else hi = m; }
                bks[k] = lo;
                hi = sb[k + 1];
                while (lo < hi) { int m = (lo + hi) >> 1; if (lat[m] < la + 1) lo = m + 1; else hi = m; }
                eks[k] = lo;
            }
            int p0 = bks[0], p1 = bks[1], p2 = bks[2];
            const float q = qw[la];
            int prev = -2, rstart = ent, rcnt = 0, rlo0 = 0;
            while (p0 < eks[0] || p1 < eks[1] || p2 < eks[2]) {
                int l0 = (p0 < eks[0]) ? lon[p0] : 0x7fffffff;
                int l1 = (p1 < eks[1]) ? lon[p1] : 0x7fffffff;
                int l2 = (p2 < eks[2]) ? lon[p2] : 0x7fffffff;
                int lm = min(l0, min(l1, l2));
                float w0 = 0.f, w1 = 0.f, w2 = 0.f;
                if (l0 == lm) { w0 = vals[p0] * q; p0++; }
                if (l1 == lm) { w1 = vals[p1] * q; p1++; }
                if (l2 == lm) { w2 = vals[p2] * q; p2++; }
                if (w0 == 0.f && w1 == 0.f && w2 == 0.f) continue;
                if (rcnt > 0 && lm != prev + 1) {
                    int pad = (4 - (rcnt & 3)) & 3;
                    if (pass == 1) {
                        for (int z = 0; z < pad; z++)
                            EMIT_ENTRY(wabs + rstart + rcnt + z, 0.f, 0.f, 0.f)
                        int ri = rbase + runs;
                        if (ri < RSLOT)
                            g_runs[t * RSLOT + ri] =
                                make_int4(la, rlo0, rcnt + pad, wabs + rstart);
                    }
                    runs++;
                    ent = rstart + rcnt + pad;
                    rstart = ent; rcnt = 0;
                }
                if (rcnt == 0) rlo0 = lm;
                if (pass == 1)
                    EMIT_ENTRY(wabs + rstart + rcnt, w0, w1, w2)
                rcnt++;
                ent = rstart + rcnt;
                prev = lm;
            }
            if (rcnt > 0) {
                int pad = (4 - (rcnt & 3)) & 3;
                if (pass == 1) {
                    for (int z = 0; z < pad; z++)
                        EMIT_ENTRY(wabs + rstart + rcnt + z, 0.f, 0.f, 0.f)
                    int ri = rbase + runs;
                    if (ri < RSLOT)
                        g_runs[t * RSLOT + ri] =
                            make_int4(la, rlo0, rcnt + pad, wabs + rstart);
                }
                runs++;
                ent = rstart + rcnt + pad;
            }
        }
        if (pass == 0) {
            entc = ent; runsc = runs;
            int ei = entc, ri = runsc;
            #pragma unroll
            for (int d = 1; d < 32; d <<= 1) {
                int v = __shfl_up_sync(0xffffffffu, ei, d);
                int u = __shfl_up_sync(0xffffffffu, ri, d);
                if (lane >= d) { ei += v; ri += u; }
            }
            wabs  = t * WSLOT + (ei - entc);
            rbase = ri - runsc;
            if (lane == 31) g_rcnt[t] = min(ri, RSLOT);
        }
    }
    #undef EMIT_ENTRY
}

// ---------------------------------------------------------------------------
// Stage 1: gather. Rolling column window on padded x rows (one wrap/iter),
// pre-duplicated weight pairs (no packing movs). Writes z fp16 M-major.
// ---------------------------------------------------------------------------
__global__ void __launch_bounds__(256, 2)
gather_kernel() {
    const int tid  = threadIdx.x;
    const int warp = tid >> 5;
    const int lane = tid & 31;

    const int yb = blockIdx.y;
    const int t  = (yb & 1) ? (NLAT - 1 - (yb >> 1)) : (yb >> 1);   // pole-first
    const int b  = blockIdx.z;
    const int p0 = blockIdx.x * PT;
    const int pbase = p0 + warp * 4;
    int pm = pbase; if (pm >= NLON) pm -= NLON;

    const int nruns = g_rcnt[t];
    const int4* runs = g_runs + (size_t)t * RSLOT;
    const float4* xb = (const float4*)(g_xt + (size_t)b * NLAT * XPAD * CIN);

    unsigned long long a2[3][4][2];
    #pragma unroll
    for (int k = 0; k < 3; k++)
        #pragma unroll
        for (int q = 0; q < 4; q++) { a2[k][q][0] = 0ull; a2[k][q][1] = 0ull; }

    for (int r = 0; r < nruns; r++) {
        const int4 rn = __ldg(&runs[r]);
        const int la   = rn.x;
        const int cnt  = rn.z;                 // multiple of 4
        const float4* wp4 = (const float4*)(g_rwp + (size_t)rn.w * 6);
        const int rowb = la * XPAD;

        int col0 = rn.y + pm;
        if (col0 >= NLON) col0 -= NLON;        // <= 359; loads up to col0+2 <= 361 < XPAD
        F4U w0v, w1v, w2v;
        w0v.f = xb[(size_t)(rowb + col0)     * 32 + lane];
        w1v.f = xb[(size_t)(rowb + col0 + 1) * 32 + lane];
        w2v.f = xb[(size_t)(rowb + col0 + 2) * 32 + lane];
        int colx = col0 + 2;
        if (colx >= NLON) colx -= NLON;        // <= 359

        for (int j4 = 0; j4 < cnt; j4 += 4) {
            // batch-load next 4 columns: colx+1..colx+4 <= 363 < XPAD
            F4U nw0, nw1, nw2, nw3;
            nw0.f = xb[(size_t)(rowb + colx + 1) * 32 + lane];
            nw1.f = xb[(size_t)(rowb + colx + 2) * 32 + lane];
            nw2.f = xb[(size_t)(rowb + colx + 3) * 32 + lane];
            nw3.f = xb[(size_t)(rowb + colx + 4) * 32 + lane];
            colx += 4;
            if (colx >= NLON) colx -= NLON;

            F4U u0, u1, u2, u3, u4, u5;        // pre-duplicated weight pairs
            u0.f = __ldg(wp4 + 0); u1.f = __ldg(wp4 + 1); u2.f = __ldg(wp4 + 2);
            u3.f = __ldg(wp4 + 3); u4.f = __ldg(wp4 + 4); u5.f = __ldg(wp4 + 5);
            wp4 += 6;

            #define DO_ENTRY(K0, K1, K2, V0, V1, V2, V3)                          \
            {                                                                     \
                fma2(a2[0][0][0], K0, V0.u[0]); fma2(a2[0][0][1], K0, V0.u[1]);   \
                fma2(a2[1][0][0], K1, V0.u[0]); fma2(a2[1][0][1], K1, V0.u[1]);   \
                fma2(a2[2][0][0], K2, V0.u[0]); fma2(a2[2][0][1], K2, V0.u[1]);   \
                fma2(a2[0][1][0], K0, V1.u[0]); fma2(a2[0][1][1], K0, V1.u[1]);   \
                fma2(a2[1][1][0], K1, V1.u[0]); fma2(a2[1][1][1], K1, V1.u[1]);   \
                fma2(a2[2][1][0], K2, V1.u[0]); fma2(a2[2][1][1], K2, V1.u[1]);   \
                fma2(a2[0][2][0], K0, V2.u[0]); fma2(a2[0][2][1], K0, V2.u[1]);   \
                fma2(a2[1][2][0], K1, V2.u[0]); fma2(a2[1][2][1], K1, V2.u[1]);   \
                fma2(a2[2][2][0], K2, V2.u[0]); fma2(a2[2][2][1], K2, V2.u[1]);   \
                fma2(a2[0][3][0], K0, V3.u[0]); fma2(a2[0][3][1], K0, V3.u[1]);   \
                fma2(a2[1][3][0], K1, V3.u[0]); fma2(a2[1][3][1], K1, V3.u[1]);   \
                fma2(a2[2][3][0], K2, V3.u[0]); fma2(a2[2][3][1], K2, V3.u[1]);   \
            }
            DO_ENTRY(u0.u[0], u0.u[1], u1.u[0], w0v, w1v, w2v, nw0)
            DO_ENTRY(u1.u[1], u2.u[0], u2.u[1], w1v, w2v, nw0, nw1)
            DO_ENTRY(u3.u[0], u3.u[1], u4.u[0], w2v, nw0, nw1, nw2)
            DO_ENTRY(u4.u[1], u5.u[0], u5.u[1], nw0, nw1, nw2, nw3)
            #undef DO_ENTRY
            w0v = nw1; w1v = nw2; w2v = nw3;
        }
    }

    // store z[m][ck] as fp16: ck = (lane*4 + c)*3 + k, 12 halves per q
    if (pbase < NLON) {
        const size_t mb = (size_t)(b * NLAT + t) * NLON + pbase;
        #pragma unroll
        for (int q = 0; q < 4; q++) {
            __half2* zp = (__half2*)(g_zh + (mb + q) * (size_t)CK + lane * 12);
            U2F c0k0, c0k1, c0k2, c1k0, c1k1, c1k2;
            c0k0.u = a2[0][q][0]; c0k1.u = a2[1][q][0]; c0k2.u = a2[2][q][0];
            c1k0.u = a2[0][q][1]; c1k1.u = a2[1][q][1]; c1k2.u = a2[2][q][1];
            zp[0] = __floats2half2_rn(c0k0.f.x, c0k1.f.x);
            zp[1] = __floats2half2_rn(c0k2.f.x, c0k0.f.y);
            zp[2] = __floats2half2_rn(c0k1.f.y, c0k2.f.y);
            zp[3] = __floats2half2_rn(c1k0.f.x, c1k1.f.x);
            zp[4] = __floats2half2_rn(c1k2.f.x, c1k0.f.y);
            zp[5] = __floats2half2_rn(c1k1.f.y, c1k2.f.y);
        }
    }
}

// ---------------------------------------------------------------------------
// Stage 2: fp16 mma.sync m16n8k16 GEMM, 3-stage cp.async pipeline (unchanged).
// ---------------------------------------------------------------------------
__global__ void __launch_bounds__(256, 2)
gemm_mma_kernel(const float* __restrict__ bias, float* __restrict__ out) {
    extern __shared__ __align__(16) char smem[];     // [NSTG][STGB]
    __shared__ float s_bias[COUT];

    const int tid  = threadIdx.x;
    const int warp = tid >> 5;
    const int lane = tid & 31;
    const int g    = lane >> 2;
    const int tg   = lane & 3;
    const int wm   = warp & 3;
    const int wn   = warp >> 2;
    const int m0   = blockIdx.x * MTILE;

    const uint32_t sbase = smem_u32(smem);
    const int lrw = tid >> 1;
    const int lsg = (tid & 1) * 2;

    if (tid < COUT) s_bias[tid] = __ldg(bias + tid);

    const uint32_t lrow = (uint32_t)(lane & 15);
    const uint32_t lsel = (uint32_t)(lane >> 4) * 16;
    uint32_t a_adr[2], b_adr[4];
    #pragma unroll
    for (int mt = 0; mt < 2; mt++)
        a_adr[mt] = sbase + (wm * 32 + mt * 16 + lrow) * SROWB + lsel;
    #pragma unroll
    for (int pr = 0; pr < 4; pr++)
        b_adr[pr] = sbase + CHNKB + (wn * 64 + pr * 16 + lrow) * SROWB + lsel;

    float acc[2][8][4];
    #pragma unroll
    for (int mt = 0; mt < 2; mt++)
        #pragma unroll
        for (int nt = 0; nt < 8; nt++)
            #pragma unroll
            for (int i = 0; i < 4; i++) acc[mt][nt][i] = 0.f;

    #define LOAD_CHUNK(CH, BUFI)                                                   \
    {                                                                              \
        const uint32_t sa = sbase + (uint32_t)(BUFI) * STGB;                       \
        _Pragma("unroll")                                                          \
        for (int s = 0; s < 2; s++) {                                              \
            const int seg = lsg + s;                                               \
            const uint32_t so = (uint32_t)(lrw * SROWB + seg * 16);                \
            cpasync16(sa + so, &g_zh[(size_t)(m0 + lrw) * CK + (CH) * KCH + seg * 8]); \
            cpasync16(sa + CHNKB + so, &g_wh[lrw * CK + (CH) * KCH + seg * 8]);    \
        }                                                                          \
        cp_commit();                                                               \
    }

    LOAD_CHUNK(0, 0)
    LOAD_CHUNK(1, 1)

    for (int ch = 0; ch < NCH; ch++) {
        if (ch + 1 < NCH) cp_wait<1>(); else cp_wait<0>();
        __syncthreads();
        if (ch + 2 < NCH) { LOAD_CHUNK(ch + 2, (ch + 2) % NSTG) }

        const uint32_t bufo = (uint32_t)(ch % NSTG) * STGB;
        #pragma unroll
        for (int ksk = 0; ksk < 2; ksk++) {
            const uint32_t ko = bufo + ksk * 32;
            uint32_t afr[2][4];
            #pragma unroll
            for (int mt = 0; mt < 2; mt++)
                ldsm_x4(afr[mt][0], afr[mt][1], afr[mt][2], afr[mt][3],
                        a_adr[mt] + ko);
            #pragma unroll
            for (int pr = 0; pr < 4; pr++) {
                uint32_t r0, r1, r2, r3;
                ldsm_x4(r0, r1, r2, r3, b_adr[pr] + ko);
                mma_f16(acc[0][2 * pr],     afr[0], r0, r2);
                mma_f16(acc[1][2 * pr],     afr[1], r0, r2);
                mma_f16(acc[0][2 * pr + 1], afr[0], r1, r3);
                mma_f16(acc[1][2 * pr + 1], afr[1], r1, r3);
            }
        }
    }

    #pragma unroll
    for (int mt = 0; mt < 2; mt++) {
        const int mlo = m0 + wm * 32 + mt * 16 + g;
        const int mhi = mlo + 8;
        const bool vlo = (mlo < MTOT), vhi = (mhi < MTOT);
        float* plo = nullptr;
        float* phi = nullptr;
        if (vlo) { int bb = mlo / CHW; plo = out + (size_t)bb * COUT * CHW + (mlo - bb * CHW); }
        if (vhi) { int bb = mhi / CHW; phi = out + (size_t)bb * COUT * CHW + (mhi - bb * CHW); }
        #pragma unroll
        for (int nt = 0; nt < 8; nt++) {
            const int f0 = wn * 64 + nt * 8 + tg * 2;
            const float b0 = s_bias[f0], b1 = s_bias[f0 + 1];
            if (vlo) {
                plo[(size_t)f0 * CHW]       = acc[mt][nt][0] + b0;
                plo[(size_t)(f0 + 1) * CHW] = acc[mt][nt][1] + b1;
            }
            if (vhi) {
                phi[(size_t)f0 * CHW]       = acc[mt][nt][2] + b0;
                phi[(size_t)(f0 + 1) * CHW] = acc[mt][nt][3] + b1;
            }
        }
    }
    #undef LOAD_CHUNK
}

// ---------------------------------------------------------------------------
// Launch.
// ---------------------------------------------------------------------------
extern "C" void kernel_launch(void* const* d_in, const int* in_sizes, int n_in,
                              void* d_out, int out_size) {
    const float* x      = (const float*)d_in[0];
    const float* qw     = (const float*)d_in[1];
    const float* vals   = (const float*)d_in[2];
    const float* weight = (const float*)d_in[3];
    const float* bias   = (const float*)d_in[4];
    const int*   seg    = (const int*)d_in[5];
    const int*   lat    = (const int*)d_in[6];
    const int*   lon    = (const int*)d_in[7];
    const int    nnz    = in_sizes[2];

    dim3 tgrid((CHW + 31) / 32, CIN / 32, BSZ);
    transpose_kernel<<<tgrid, dim3(32, 8)>>>(x);
    wconv_kernel<<<(COUT * CK + 255) / 256, 256>>>(weight);
    merge_kernel<<<(NLAT * 32 + 127) / 128, 128>>>(seg, lat, lon, vals, qw, nnz);

    dim3 ggrid(NPT, NLAT, BSZ);
    gather_kernel<<<ggrid, 256>>>();

    const int dyn_bytes = NSTG * STGB;   // 86016
    cudaFuncSetAttribute(gemm_mma_kernel,
                         cudaFuncAttributeMaxDynamicSharedMemorySize, dyn_bytes);
    gemm_mma_kernel<<<MBLK, 256, dyn_bytes>>>(bias, (float*)d_out);
}

// round 12
// speedup vs baseline: 1.0707x; 1.0707x over previous
#include <cuda_runtime.h>
#include <cuda_fp16.h>
#include <cstdint>

// Problem constants
#define NLAT 181
#define NLON 360
#define CIN  128
#define COUT 128
#define KS   3
#define BSZ  2
#define CHW  (NLAT * NLON)     // 65160
#define CK   (CIN * KS)        // 384
#define PT   24                // gather p-tile (15 * 24 = 360 exact)
#define NPT  15
#define GTHR 384               // gather threads: 6 p-groups x 2 channel halves
#define MTOT  (BSZ * CHW)      // 130320
#define MTILE 128
#define MBLK  ((MTOT + MTILE - 1) / MTILE)   // 1019
#define MPADL (MBLK * MTILE)                 // 130432
#define WSLOT 4096
#define RSLOT 512
#define KCH   32               // GEMM K-chunk (halves)
#define NCH   (CK / KCH)       // 12
#define SROWB 112              // smem row stride bytes
#define CHNKB (128 * SROWB)
#define STGB  (2 * CHNKB)
#define NSTG  3

// Scratch (device globals — allocation-free; zero-init so padded z rows are 0)
__device__ float  g_xt[(size_t)BSZ * CHW * CIN];   // x transposed: [b][h*w][c]
__device__ float4 g_rw[NLAT * WSLOT];              // run weights {w0,w1,w2,0}
__device__ int4   g_runs[NLAT * RSLOT];            // {la, lo0, cnt_padded, wabs}
__device__ int    g_rcnt[NLAT];
__device__ __half g_zh[(size_t)MPADL * CK];        // z M-major [m][ck], fp16
__device__ __half g_wh[COUT * CK];                 // W [f][ck], fp16

// ---------------- helpers ----------------
__device__ __forceinline__ void fma2(unsigned long long& d,
                                     unsigned long long a,
                                     unsigned long long b) {
    asm("fma.rn.f32x2 %0, %1, %2, %0;" : "+l"(d) : "l"(a), "l"(b));
}
__device__ __forceinline__ unsigned long long pack2(float x, float y) {
    unsigned long long r;
    asm("mov.b64 %0, {%1, %2};" : "=l"(r) : "f"(x), "f"(y));
    return r;
}
union U2F { unsigned long long u; float2 f; };

__device__ __forceinline__ uint32_t smem_u32(const void* p) {
    uint32_t a;
    asm("{ .reg .u64 t; cvta.to.shared.u64 t, %1; cvt.u32.u64 %0, t; }"
        : "=r"(a) : "l"(p));
    return a;
}
__device__ __forceinline__ void cpasync16(uint32_t s, const void* g) {
    asm volatile("cp.async.cg.shared.global [%0], [%1], 16;" :: "r"(s), "l"(g));
}
__device__ __forceinline__ void cp_commit() {
    asm volatile("cp.async.commit_group;" ::: "memory");
}
template <int N>
__device__ __forceinline__ void cp_wait() {
    asm volatile("cp.async.wait_group %0;" :: "n"(N) : "memory");
}
__device__ __forceinline__ void mma_f16(float* d, const uint32_t* a,
                                        uint32_t b0, uint32_t b1) {
    asm volatile(
        "mma.sync.aligned.m16n8k16.row.col.f32.f16.f16.f32 "
        "{%0,%1,%2,%3}, {%4,%5,%6,%7}, {%8,%9}, {%0,%1,%2,%3};"
        : "+f"(d[0]), "+f"(d[1]), "+f"(d[2]), "+f"(d[3])
        : "r"(a[0]), "r"(a[1]), "r"(a[2]), "r"(a[3]), "r"(b0), "r"(b1));
}
__device__ __forceinline__ void ldsm_x4(uint32_t& r0, uint32_t& r1,
                                        uint32_t& r2, uint32_t& r3, uint32_t addr) {
    asm volatile("ldmatrix.sync.aligned.m8n8.x4.shared.b16 {%0,%1,%2,%3}, [%4];"
                 : "=r"(r0), "=r"(r1), "=r"(r2), "=r"(r3) : "r"(addr));
}

// ---------------------------------------------------------------------------
// Transpose x[b][c][hw] -> g_xt[b][hw][c]
// ---------------------------------------------------------------------------
__global__ void transpose_kernel(const float* __restrict__ x) {
    __shared__ float tile[32][33];
    const int hw0 = blockIdx.x * 32;
    const int c0  = blockIdx.y * 32;
    const int b   = blockIdx.z;
    const int tx = threadIdx.x, ty = threadIdx.y;
    #pragma unroll
    for (int i = 0; i < 4; i++) {
        int c  = c0 + ty + i * 8;
        int hw = hw0 + tx;
        if (hw < CHW)
            tile[ty + i * 8][tx] = x[((size_t)b * CIN + c) * CHW + hw];
    }
    __syncthreads();
    #pragma unroll
    for (int i = 0; i < 4; i++) {
        int hw = hw0 + ty + i * 8;
        int c  = c0 + tx;
        if (hw < CHW)
            g_xt[((size_t)b * CHW + hw) * CIN + c] = tile[tx][ty + i * 8];
    }
}

// W[f][ck] -> fp16 copy
__global__ void wconv_kernel(const float* __restrict__ w) {
    int i = blockIdx.x * 256 + threadIdx.x;
    if (i < COUT * CK) g_wh[i] = __float2half_rn(w[i]);
}

// ---------------------------------------------------------------------------
// Merge: warp per t. Emits per-(t,la) runs of consecutive lons with
// branch-free weight triples, zero-padded to multiples of 4 entries.
// ---------------------------------------------------------------------------
__global__ void merge_kernel(const int* __restrict__ seg,
                             const int* __restrict__ lat,
                             const int* __restrict__ lon,
                             const float* __restrict__ vals,
                             const float* __restrict__ qw,
                             int nnz) {
    const int t    = (blockIdx.x * blockDim.x + threadIdx.x) >> 5;
    const int lane = threadIdx.x & 31;
    if (t >= NLAT) return;

    int sb[4];
    #pragma unroll
    for (int k = 0; k < 4; k++) {
        const int j = t * KS + k;
        int lo = 0, hi = nnz;
        while (lo < hi) {
            int m = (lo + hi) >> 1;
            int sgv = seg[m];
            int key = (sgv % NLAT) * KS + (sgv / NLAT);
            if (key < j) lo = m + 1; else hi = m;
        }
        sb[k] = lo;
    }

    const int wlim = (t + 1) * WSLOT;
    int wabs = 0, rbase = 0;
    int entc = 0, runsc = 0;

    for (int pass = 0; pass < 2; pass++) {
        int ent = 0, runs = 0;
        for (int la = lane; la < NLAT; la += 32) {
            int bks[3], eks[3];
            #pragma unroll
            for (int k = 0; k < 3; k++) {
                int lo = sb[k], hi = sb[k + 1];
                while (lo < hi) { int m = (lo + hi) >> 1; if (lat[m] < la) lo = m + 1; else hi = m; }
                bks[k] = lo;
                hi = sb[k + 1];
                while (lo < hi) { int m = (lo + hi) >> 1; if (lat[m] < la + 1) lo = m + 1; else hi = m; }
                eks[k] = lo;
            }
            int p0 = bks[0], p1 = bks[1], p2 = bks[2];
            const float q = qw[la];
            int prev = -2, rstart = ent, rcnt = 0, rlo0 = 0;
            while (p0 < eks[0] || p1 < eks[1] || p2 < eks[2]) {
                int l0 = (p0 < eks[0]) ? lon[p0] : 0x7fffffff;
                int l1 = (p1 < eks[1]) ? lon[p1] : 0x7fffffff;
                int l2 = (p2 < eks[2]) ? lon[p2] : 0x7fffffff;
                int lm = min(l0, min(l1, l2));
                float w0 = 0.f, w1 = 0.f, w2 = 0.f;
                if (l0 == lm) { w0 = vals[p0] * q; p0++; }
                if (l1 == lm) { w1 = vals[p1] * q; p1++; }
                if (l2 == lm) { w2 = vals[p2] * q; p2++; }
                if (w0 == 0.f && w1 == 0.f && w2 == 0.f) continue;
                if (rcnt > 0 && lm != prev + 1) {
                    int pad = (4 - (rcnt & 3)) & 3;
                    if (pass == 1) {
                        for (int z = 0; z < pad; z++) {
                            int ai = wabs + rstart + rcnt + z;
                            if (ai < wlim) g_rw[ai] = make_float4(0.f, 0.f, 0.f, 0.f);
                        }
                        int ri = rbase + runs;
                        if (ri < RSLOT)
                            g_runs[t * RSLOT + ri] =
                                make_int4(la, rlo0, rcnt + pad, wabs + rstart);
                    }
                    runs++;
                    ent = rstart + rcnt + pad;
                    rstart = ent; rcnt = 0;
                }
                if (rcnt == 0) rlo0 = lm;
                if (pass == 1) {
                    int ai = wabs + rstart + rcnt;
                    if (ai < wlim) g_rw[ai] = make_float4(w0, w1, w2, 0.f);
                }
                rcnt++;
                ent = rstart + rcnt;
                prev = lm;
            }
            if (rcnt > 0) {
                int pad = (4 - (rcnt & 3)) & 3;
                if (pass == 1) {
                    for (int z = 0; z < pad; z++) {
                        int ai = wabs + rstart + rcnt + z;
                        if (ai < wlim) g_rw[ai] = make_float4(0.f, 0.f, 0.f, 0.f);
                    }
                    int ri = rbase + runs;
                    if (ri < RSLOT)
                        g_runs[t * RSLOT + ri] =
                            make_int4(la, rlo0, rcnt + pad, wabs + rstart);
                }
                runs++;
                ent = rstart + rcnt + pad;
            }
        }
        if (pass == 0) {
            entc = ent; runsc = runs;
            int ei = entc, ri = runsc;
            #pragma unroll
            for (int d = 1; d < 32; d <<= 1) {
                int v = __shfl_up_sync(0xffffffffu, ei, d);
                int u = __shfl_up_sync(0xffffffffu, ri, d);
                if (lane >= d) { ei += v; ri += u; }
            }
            wabs  = t * WSLOT + (ei - entc);
            rbase = ri - runsc;
            if (lane == 31) g_rcnt[t] = min(ri, RSLOT);
        }
    }
}

// ---------------------------------------------------------------------------
// Stage 1: gather, channel-split warps. Warp = 4 p's x 64 channels (float2
// lanes); block = 384 thr = 6 p-groups x 2 channel halves. Rolling column
// window, 12 fma2 per entry per warp. Writes z fp16 M-major.
// ---------------------------------------------------------------------------
__global__ void __launch_bounds__(GTHR, 2)
gather_kernel() {
    const int tid  = threadIdx.x;
    const int warp = tid >> 5;
    const int lane = tid & 31;
    const int pgrp = warp >> 1;          // 0..5
    const int chal = warp & 1;           // channel half

    const int yb = blockIdx.y;
    const int t  = (yb & 1) ? (NLAT - 1 - (yb >> 1)) : (yb >> 1);   // pole-first
    const int b  = blockIdx.z;
    const int pbase = blockIdx.x * PT + pgrp * 4;   // always < 360

    const int nruns = g_rcnt[t];
    const int4* runs = g_runs + (size_t)t * RSLOT;
    const float2* xb = (const float2*)(g_xt + (size_t)b * CHW * CIN);
    const int coff = chal * 32 + lane;   // float2 index within a 64-float2 row

    unsigned long long a2[3][4];         // [k][q], each = 2 channels packed
    #pragma unroll
    for (int k = 0; k < 3; k++)
        #pragma unroll
        for (int q = 0; q < 4; q++) a2[k][q] = 0ull;

    for (int r = 0; r < nruns; r++) {
        const int4 rn = __ldg(&runs[r]);
        const int la   = rn.x;
        const int cnt  = rn.z;           // multiple of 4
        const float4* wp = g_rw + rn.w;
        const int rowb = la * NLON;

        int col = rn.y + pbase;
        if (col >= NLON) col -= NLON;
        if (col >= NLON) col -= NLON;
        int c1 = col + 1; if (c1 >= NLON) c1 -= NLON;
        int c2 = c1 + 1;  if (c2 >= NLON) c2 -= NLON;

        U2F w0v, w1v, w2v;               // window: cols j, j+1, j+2
        w0v.f = xb[(size_t)(rowb + col) * 64 + coff];
        w1v.f = xb[(size_t)(rowb + c1)  * 64 + coff];
        w2v.f = xb[(size_t)(rowb + c2)  * 64 + coff];
        int colx = c2;

        for (int j4 = 0; j4 < cnt; j4 += 4) {
            int n0 = colx + 1; if (n0 >= NLON) n0 -= NLON;
            int n1 = colx + 2; if (n1 >= NLON) n1 -= NLON;
            int n2 = colx + 3; if (n2 >= NLON) n2 -= NLON;
            int n3 = colx + 4; if (n3 >= NLON) n3 -= NLON;
            colx = n3;
            U2F nw0, nw1, nw2, nw3;
            nw0.f = xb[(size_t)(rowb + n0) * 64 + coff];
            nw1.f = xb[(size_t)(rowb + n1) * 64 + coff];
            nw2.f = xb[(size_t)(rowb + n2) * 64 + coff];
            nw3.f = xb[(size_t)(rowb + n3) * 64 + coff];

            float4 wa = __ldg(&wp[j4 + 0]);
            float4 wb = __ldg(&wp[j4 + 1]);
            float4 wc = __ldg(&wp[j4 + 2]);
            float4 wd = __ldg(&wp[j4 + 3]);

            // entry u uses columns j4+u .. j4+u+3 (V0..V3 for q=0..3)
            #define DO_ENTRY(W, V0, V1, V2, V3)                                   \
            {                                                                     \
                unsigned long long k0 = pack2(W.x, W.x);                          \
                unsigned long long k1 = pack2(W.y, W.y);                          \
                unsigned long long k2 = pack2(W.z, W.z);                          \
                fma2(a2[0][0], k0, V0.u); fma2(a2[1][0], k1, V0.u);               \
                fma2(a2[2][0], k2, V0.u);                                         \
                fma2(a2[0][1], k0, V1.u); fma2(a2[1][1], k1, V1.u);               \
                fma2(a2[2][1], k2, V1.u);                                         \
                fma2(a2[0][2], k0, V2.u); fma2(a2[1][2], k1, V2.u);               \
                fma2(a2[2][2], k2, V2.u);                                         \
                fma2(a2[0][3], k0, V3.u); fma2(a2[1][3], k1, V3.u);               \
                fma2(a2[2][3], k2, V3.u);                                         \
            }
            DO_ENTRY(wa, w0v, w1v, w2v, nw0)
            DO_ENTRY(wb, w1v, w2v, nw0, nw1)
            DO_ENTRY(wc, w2v, nw0, nw1, nw2)
            DO_ENTRY(wd, nw0, nw1, nw2, nw3)
            #undef DO_ENTRY
            w0v = nw1; w1v = nw2; w2v = nw3;
        }
    }

    // store z[m][ck] as fp16: channels c0 = 64*chal + 2*lane, c0+1;
    // ck = c*3 + k -> 6 consecutive halves = 3 half2 per q.
    {
        const size_t mb = (size_t)(b * NLAT + t) * NLON + pbase;
        const int ckb = (chal * 64 + 2 * lane) * 3;
        #pragma unroll
        for (int q = 0; q < 4; q++) {
            __half2* zp = (__half2*)(g_zh + (mb + q) * (size_t)CK + ckb);
            U2F k0, k1, k2;
            k0.u = a2[0][q]; k1.u = a2[1][q]; k2.u = a2[2][q];
            zp[0] = __floats2half2_rn(k0.f.x, k1.f.x);   // (c0,k0)(c0,k1)
            zp[1] = __floats2half2_rn(k2.f.x, k0.f.y);   // (c0,k2)(c1,k0)
            zp[2] = __floats2half2_rn(k1.f.y, k2.f.y);   // (c1,k1)(c1,k2)
        }
    }
}

// ---------------------------------------------------------------------------
// Stage 2: fp16 mma.sync m16n8k16 GEMM, 3-stage cp.async pipeline (R10).
// ---------------------------------------------------------------------------
__global__ void __launch_bounds__(256, 2)
gemm_mma_kernel(const float* __restrict__ bias, float* __restrict__ out) {
    extern __shared__ __align__(16) char smem[];     // [NSTG][STGB]
    __shared__ float s_bias[COUT];

    const int tid  = threadIdx.x;
    const int warp = tid >> 5;
    const int lane = tid & 31;
    const int g    = lane >> 2;
    const int tg   = lane & 3;
    const int wm   = warp & 3;
    const int wn   = warp >> 2;
    const int m0   = blockIdx.x * MTILE;

    const uint32_t sbase = smem_u32(smem);
    const int lrw = tid >> 1;
    const int lsg = (tid & 1) * 2;

    if (tid < COUT) s_bias[tid] = __ldg(bias + tid);

    const uint32_t lrow = (uint32_t)(lane & 15);
    const uint32_t lsel = (uint32_t)(lane >> 4) * 16;
    uint32_t a_adr[2], b_adr[4];
    #pragma unroll
    for (int mt = 0; mt < 2; mt++)
        a_adr[mt] = sbase + (wm * 32 + mt * 16 + lrow) * SROWB + lsel;
    #pragma unroll
    for (int pr = 0; pr < 4; pr++)
        b_adr[pr] = sbase + CHNKB + (wn * 64 + pr * 16 + lrow) * SROWB + lsel;

    float acc[2][8][4];
    #pragma unroll
    for (int mt = 0; mt < 2; mt++)
        #pragma unroll
        for (int nt = 0; nt < 8; nt++)
            #pragma unroll
            for (int i = 0; i < 4; i++) acc[mt][nt][i] = 0.f;

    #define LOAD_CHUNK(CH, BUFI)                                                   \
    {                                                                              \
        const uint32_t sa = sbase + (uint32_t)(BUFI) * STGB;                       \
        _Pragma("unroll")                                                          \
        for (int s = 0; s < 2; s++) {                                              \
            const int seg = lsg + s;                                               \
            const uint32_t so = (uint32_t)(lrw * SROWB + seg * 16);                \
            cpasync16(sa + so, &g_zh[(size_t)(m0 + lrw) * CK + (CH) * KCH + seg * 8]); \
            cpasync16(sa + CHNKB + so, &g_wh[lrw * CK + (CH) * KCH + seg * 8]);    \
        }                                                                          \
        cp_commit();                                                               \
    }

    LOAD_CHUNK(0, 0)
    LOAD_CHUNK(1, 1)

    for (int ch = 0; ch < NCH; ch++) {
        if (ch + 1 < NCH) cp_wait<1>(); else cp_wait<0>();
        __syncthreads();
        if (ch + 2 < NCH) { LOAD_CHUNK(ch + 2, (ch + 2) % NSTG) }

        const uint32_t bufo = (uint32_t)(ch % NSTG) * STGB;
        #pragma unroll
        for (int ksk = 0; ksk < 2; ksk++) {
            const uint32_t ko = bufo + ksk * 32;
            uint32_t afr[2][4];
            #pragma unroll
            for (int mt = 0; mt < 2; mt++)
                ldsm_x4(afr[mt][0], afr[mt][1], afr[mt][2], afr[mt][3],
                        a_adr[mt] + ko);
            #pragma unroll
            for (int pr = 0; pr < 4; pr++) {
                uint32_t r0, r1, r2, r3;
                ldsm_x4(r0, r1, r2, r3, b_adr[pr] + ko);
                mma_f16(acc[0][2 * pr],     afr[0], r0, r2);
                mma_f16(acc[1][2 * pr],     afr[1], r0, r2);
                mma_f16(acc[0][2 * pr + 1], afr[0], r1, r3);
                mma_f16(acc[1][2 * pr + 1], afr[1], r1, r3);
            }
        }
    }

    #pragma unroll
    for (int mt = 0; mt < 2; mt++) {
        const int mlo = m0 + wm * 32 + mt * 16 + g;
        const int mhi = mlo + 8;
        const bool vlo = (mlo < MTOT), vhi = (mhi < MTOT);
        float* plo = nullptr;
        float* phi = nullptr;
        if (vlo) { int bb = mlo / CHW; plo = out + (size_t)bb * COUT * CHW + (mlo - bb * CHW); }
        if (vhi) { int bb = mhi / CHW; phi = out + (size_t)bb * COUT * CHW + (mhi - bb * CHW); }
        #pragma unroll
        for (int nt = 0; nt < 8; nt++) {
            const int f0 = wn * 64 + nt * 8 + tg * 2;
            const float b0 = s_bias[f0], b1 = s_bias[f0 + 1];
            if (vlo) {
                plo[(size_t)f0 * CHW]       = acc[mt][nt][0] + b0;
                plo[(size_t)(f0 + 1) * CHW] = acc[mt][nt][1] + b1;
            }
            if (vhi) {
                phi[(size_t)f0 * CHW]       = acc[mt][nt][2] + b0;
                phi[(size_t)(f0 + 1) * CHW] = acc[mt][nt][3] + b1;
            }
        }
    }
    #undef LOAD_CHUNK
}

// ---------------------------------------------------------------------------
// Launch.
// ---------------------------------------------------------------------------
extern "C" void kernel_launch(void* const* d_in, const int* in_sizes, int n_in,
                              void* d_out, int out_size) {
    const float* x      = (const float*)d_in[0];
    const float* qw     = (const float*)d_in[1];
    const float* vals   = (const float*)d_in[2];
    const float* weight = (const float*)d_in[3];
    const float* bias   = (const float*)d_in[4];
    const int*   seg    = (const int*)d_in[5];
    const int*   lat    = (const int*)d_in[6];
    const int*   lon    = (const int*)d_in[7];
    const int    nnz    = in_sizes[2];

    dim3 tgrid((CHW + 31) / 32, CIN / 32, BSZ);
    transpose_kernel<<<tgrid, dim3(32, 8)>>>(x);
    wconv_kernel<<<(COUT * CK + 255) / 256, 256>>>(weight);
    merge_kernel<<<(NLAT * 32 + 127) / 128, 128>>>(seg, lat, lon, vals, qw, nnz);

    dim3 ggrid(NPT, NLAT, BSZ);
    gather_kernel<<<ggrid, GTHR>>>();

    const int dyn_bytes = NSTG * STGB;   // 86016
    cudaFuncSetAttribute(gemm_mma_kernel,
                         cudaFuncAttributeMaxDynamicSharedMemorySize, dyn_bytes);
    gemm_mma_kernel<<<MBLK, 256, dyn_bytes>>>(bias, (float*)d_out);
}

// round 13
// speedup vs baseline: 1.1062x; 1.0332x over previous
#include <cuda_runtime.h>
#include <cuda_fp16.h>
#include <cstdint>

// Problem constants
#define NLAT 181
#define NLON 360
#define CIN  128
#define COUT 128
#define KS   3
#define BSZ  2
#define CHW  (NLAT * NLON)     // 65160
#define CK   (CIN * KS)        // 384
#define PT   32                // gather p-tile
#define NPT  12
#define MTOT  (BSZ * CHW)      // 130320
#define MTILE 128
#define MBLK  ((MTOT + MTILE - 1) / MTILE)   // 1019
#define MPADL (MBLK * MTILE)                 // 130432
#define WSLOT 4096
#define RSLOT 512
#define KCH   32               // GEMM K-chunk (halves)
#define NCH   (CK / KCH)       // 12
#define SROWB 80               // smem row stride bytes (20 words; starts 20r%32 disjoint)
#define CHNKB (128 * SROWB)    // 10240
#define STGB  (2 * CHNKB)      // 20480 per stage (A+B)
#define NSTG  4

// Scratch (device globals — allocation-free; zero-init so padded z rows are 0)
__device__ float  g_xt[(size_t)BSZ * CHW * CIN];   // x transposed: [b][h*w][c]
__device__ float4 g_rw[NLAT * WSLOT];              // run weights {w0,w1,w2,0}
__device__ int4   g_runs[NLAT * RSLOT];            // {la, lo0, cnt_padded, wabs}
__device__ int    g_rcnt[NLAT];
__device__ __half g_zh[(size_t)MPADL * CK];        // z M-major [m][ck], fp16
__device__ __half g_wh[COUT * CK];                 // W [f][ck], fp16

// ---------------- helpers ----------------
__device__ __forceinline__ void fma2(unsigned long long& d,
                                     unsigned long long a,
                                     unsigned long long b) {
    asm("fma.rn.f32x2 %0, %1, %2, %0;" : "+l"(d) : "l"(a), "l"(b));
}
__device__ __forceinline__ unsigned long long pack2(float x, float y) {
    unsigned long long r;
    asm("mov.b64 %0, {%1, %2};" : "=l"(r) : "f"(x), "f"(y));
    return r;
}
union F4U { float4 f; unsigned long long u[2]; };
union U2F { unsigned long long u; float2 f; };

__device__ __forceinline__ uint32_t smem_u32(const void* p) {
    uint32_t a;
    asm("{ .reg .u64 t; cvta.to.shared.u64 t, %1; cvt.u32.u64 %0, t; }"
        : "=r"(a) : "l"(p));
    return a;
}
__device__ __forceinline__ void cpasync16(uint32_t s, const void* g) {
    asm volatile("cp.async.cg.shared.global [%0], [%1], 16;" :: "r"(s), "l"(g));
}
__device__ __forceinline__ void cp_commit() {
    asm volatile("cp.async.commit_group;" ::: "memory");
}
template <int N>
__device__ __forceinline__ void cp_wait() {
    asm volatile("cp.async.wait_group %0;" :: "n"(N) : "memory");
}
__device__ __forceinline__ void mma_f16(float* d, const uint32_t* a,
                                        uint32_t b0, uint32_t b1) {
    asm volatile(
        "mma.sync.aligned.m16n8k16.row.col.f32.f16.f16.f32 "
        "{%0,%1,%2,%3}, {%4,%5,%6,%7}, {%8,%9}, {%0,%1,%2,%3};"
        : "+f"(d[0]), "+f"(d[1]), "+f"(d[2]), "+f"(d[3])
        : "r"(a[0]), "r"(a[1]), "r"(a[2]), "r"(a[3]), "r"(b0), "r"(b1));
}
__device__ __forceinline__ void ldsm_x4(uint32_t& r0, uint32_t& r1,
                                        uint32_t& r2, uint32_t& r3, uint32_t addr) {
    asm volatile("ldmatrix.sync.aligned.m8n8.x4.shared.b16 {%0,%1,%2,%3}, [%4];"
                 : "=r"(r0), "=r"(r1), "=r"(r2), "=r"(r3) : "r"(addr));
}

// ---------------------------------------------------------------------------
// Transpose x[b][c][hw] -> g_xt[b][hw][c]
// ---------------------------------------------------------------------------
__global__ void transpose_kernel(const float* __restrict__ x) {
    __shared__ float tile[32][33];
    const int hw0 = blockIdx.x * 32;
    const int c0  = blockIdx.y * 32;
    const int b   = blockIdx.z;
    const int tx = threadIdx.x, ty = threadIdx.y;
    #pragma unroll
    for (int i = 0; i < 4; i++) {
        int c  = c0 + ty + i * 8;
        int hw = hw0 + tx;
        if (hw < CHW)
            tile[ty + i * 8][tx] = x[((size_t)b * CIN + c) * CHW + hw];
    }
    __syncthreads();
    #pragma unroll
    for (int i = 0; i < 4; i++) {
        int hw = hw0 + ty + i * 8;
        int c  = c0 + tx;
        if (hw < CHW)
            g_xt[((size_t)b * CHW + hw) * CIN + c] = tile[tx][ty + i * 8];
    }
}

// W[f][ck] -> fp16 copy
__global__ void wconv_kernel(const float* __restrict__ w) {
    int i = blockIdx.x * 256 + threadIdx.x;
    if (i < COUT * CK) g_wh[i] = __float2half_rn(w[i]);
}

// ---------------------------------------------------------------------------
// Merge: warp per t. Emits per-(t,la) runs of consecutive lons with
// branch-free weight triples, zero-padded to multiples of 4 entries.
// ---------------------------------------------------------------------------
__global__ void merge_kernel(const int* __restrict__ seg,
                             const int* __restrict__ lat,
                             const int* __restrict__ lon,
                             const float* __restrict__ vals,
                             const float* __restrict__ qw,
                             int nnz) {
    const int t    = (blockIdx.x * blockDim.x + threadIdx.x) >> 5;
    const int lane = threadIdx.x & 31;
    if (t >= NLAT) return;

    int sb[4];
    #pragma unroll
    for (int k = 0; k < 4; k++) {
        const int j = t * KS + k;
        int lo = 0, hi = nnz;
        while (lo < hi) {
            int m = (lo + hi) >> 1;
            int sgv = seg[m];
            int key = (sgv % NLAT) * KS + (sgv / NLAT);
            if (key < j) lo = m + 1; else hi = m;
        }
        sb[k] = lo;
    }

    const int wlim = (t + 1) * WSLOT;
    int wabs = 0, rbase = 0;
    int entc = 0, runsc = 0;

    for (int pass = 0; pass < 2; pass++) {
        int ent = 0, runs = 0;
        for (int la = lane; la < NLAT; la += 32) {
            int bks[3], eks[3];
            #pragma unroll
            for (int k = 0; k < 3; k++) {
                int lo = sb[k], hi = sb[k + 1];
                while (lo < hi) { int m = (lo + hi) >> 1; if (lat[m] < la) lo = m + 1; else hi = m; }
                bks[k] = lo;
                hi = sb[k + 1];
                while (lo < hi) { int m = (lo + hi) >> 1; if (lat[m] < la + 1) lo = m + 1; else hi = m; }
                eks[k] = lo;
            }
            int p0 = bks[0], p1 = bks[1], p2 = bks[2];
            const float q = qw[la];
            int prev = -2, rstart = ent, rcnt = 0, rlo0 = 0;
            while (p0 < eks[0] || p1 < eks[1] || p2 < eks[2]) {
                int l0 = (p0 < eks[0]) ? lon[p0] : 0x7fffffff;
                int l1 = (p1 < eks[1]) ? lon[p1] : 0x7fffffff;
                int l2 = (p2 < eks[2]) ? lon[p2] : 0x7fffffff;
                int lm = min(l0, min(l1, l2));
                float w0 = 0.f, w1 = 0.f, w2 = 0.f;
                if (l0 == lm) { w0 = vals[p0] * q; p0++; }
                if (l1 == lm) { w1 = vals[p1] * q; p1++; }
                if (l2 == lm) { w2 = vals[p2] * q; p2++; }
                if (w0 == 0.f && w1 == 0.f && w2 == 0.f) continue;
                if (rcnt > 0 && lm != prev + 1) {
                    int pad = (4 - (rcnt & 3)) & 3;
                    if (pass == 1) {
                        for (int z = 0; z < pad; z++) {
                            int ai = wabs + rstart + rcnt + z;
                            if (ai < wlim) g_rw[ai] = make_float4(0.f, 0.f, 0.f, 0.f);
                        }
                        int ri = rbase + runs;
                        if (ri < RSLOT)
                            g_runs[t * RSLOT + ri] =
                                make_int4(la, rlo0, rcnt + pad, wabs + rstart);
                    }
                    runs++;
                    ent = rstart + rcnt + pad;
                    rstart = ent; rcnt = 0;
                }
                if (rcnt == 0) rlo0 = lm;
                if (pass == 1) {
                    int ai = wabs + rstart + rcnt;
                    if (ai < wlim) g_rw[ai] = make_float4(w0, w1, w2, 0.f);
                }
                rcnt++;
                ent = rstart + rcnt;
                prev = lm;
            }
            if (rcnt > 0) {
                int pad = (4 - (rcnt & 3)) & 3;
                if (pass == 1) {
                    for (int z = 0; z < pad; z++) {
                        int ai = wabs + rstart + rcnt + z;
                        if (ai < wlim) g_rw[ai] = make_float4(0.f, 0.f, 0.f, 0.f);
                    }
                    int ri = rbase + runs;
                    if (ri < RSLOT)
                        g_runs[t * RSLOT + ri] =
                            make_int4(la, rlo0, rcnt + pad, wabs + rstart);
                }
                runs++;
                ent = rstart + rcnt + pad;
            }
        }
        if (pass == 0) {
            entc = ent; runsc = runs;
            int ei = entc, ri = runsc;
            #pragma unroll
            for (int d = 1; d < 32; d <<= 1) {
                int v = __shfl_up_sync(0xffffffffu, ei, d);
                int u = __shfl_up_sync(0xffffffffu, ri, d);
                if (lane >= d) { ei += v; ri += u; }
            }
            wabs  = t * WSLOT + (ei - entc);
            rbase = ri - runsc;
            if (lane == 31) g_rcnt[t] = min(ri, RSLOT);
        }
    }
}

// ---------------------------------------------------------------------------
// Stage 1: gather (R10 shape). Rolling column window; fma2 reordered by
// COLUMN so the 4 batch loads get 36..90 fma2 of in-warp latency cover.
// Writes z fp16 M-major.
// ---------------------------------------------------------------------------
__global__ void __launch_bounds__(256, 2)
gather_kernel() {
    const int tid  = threadIdx.x;
    const int warp = tid >> 5;
    const int lane = tid & 31;

    const int yb = blockIdx.y;
    const int t  = (yb & 1) ? (NLAT - 1 - (yb >> 1)) : (yb >> 1);   // pole-first
    const int b  = blockIdx.z;
    const int p0 = blockIdx.x * PT;
    const int pbase = p0 + warp * 4;

    const int nruns = g_rcnt[t];
    const int4* runs = g_runs + (size_t)t * RSLOT;
    const float4* xb = (const float4*)(g_xt + (size_t)b * CHW * CIN);

    unsigned long long a2[3][4][2];
    #pragma unroll
    for (int k = 0; k < 3; k++)
        #pragma unroll
        for (int q = 0; q < 4; q++) { a2[k][q][0] = 0ull; a2[k][q][1] = 0ull; }

    for (int r = 0; r < nruns; r++) {
        const int4 rn = __ldg(&runs[r]);
        const int la   = rn.x;
        const int cnt  = rn.z;                 // multiple of 4
        const float4* wp = g_rw + rn.w;
        const int rowb = la * NLON;

        int col = rn.y + pbase;
        if (col >= NLON) col -= NLON;
        if (col >= NLON) col -= NLON;
        int c1 = col + 1; if (c1 >= NLON) c1 -= NLON;
        int c2 = c1 + 1;  if (c2 >= NLON) c2 -= NLON;

        F4U w0v, w1v, w2v;
        w0v.f = xb[(size_t)(rowb + col) * 32 + lane];
        w1v.f = xb[(size_t)(rowb + c1)  * 32 + lane];
        w2v.f = xb[(size_t)(rowb + c2)  * 32 + lane];
        int colx = c2;

        for (int j4 = 0; j4 < cnt; j4 += 4) {
            // batch-load next 4 columns (used latest-first below)
            int n0 = colx + 1; if (n0 >= NLON) n0 -= NLON;
            int n1 = colx + 2; if (n1 >= NLON) n1 -= NLON;
            int n2 = colx + 3; if (n2 >= NLON) n2 -= NLON;
            int n3 = colx + 4; if (n3 >= NLON) n3 -= NLON;
            colx = n3;
            F4U nw0, nw1, nw2, nw3;
            nw0.f = xb[(size_t)(rowb + n0) * 32 + lane];
            nw1.f = xb[(size_t)(rowb + n1) * 32 + lane];
            nw2.f = xb[(size_t)(rowb + n2) * 32 + lane];
            nw3.f = xb[(size_t)(rowb + n3) * 32 + lane];

            float4 wa = __ldg(&wp[j4 + 0]);
            float4 wb = __ldg(&wp[j4 + 1]);
            float4 wc = __ldg(&wp[j4 + 2]);
            float4 wd = __ldg(&wp[j4 + 3]);

            // One column V, one entry-weight W, accumulator lane q:
            // a2[k][q] += W.k * V   (3 k's x 2 halves = 6 fma2)
            #define COLGRP(V, W, Q)                                               \
            {                                                                     \
                unsigned long long kk;                                            \
                kk = pack2(W.x, W.x);                                             \
                fma2(a2[0][Q][0], kk, V.u[0]); fma2(a2[0][Q][1], kk, V.u[1]);     \
                kk = pack2(W.y, W.y);                                             \
                fma2(a2[1][Q][0], kk, V.u[0]); fma2(a2[1][Q][1], kk, V.u[1]);     \
                kk = pack2(W.z, W.z);                                             \
                fma2(a2[2][Q][0], kk, V.u[0]); fma2(a2[2][Q][1], kk, V.u[1]);     \
            }
            // column-major order: window columns first (36 fma2 before nw0)
            COLGRP(w0v, wa, 0)
            COLGRP(w1v, wa, 1) COLGRP(w1v, wb, 0)
            COLGRP(w2v, wa, 2) COLGRP(w2v, wb, 1) COLGRP(w2v, wc, 0)
            COLGRP(nw0, wa, 3) COLGRP(nw0, wb, 2) COLGRP(nw0, wc, 1) COLGRP(nw0, wd, 0)
            COLGRP(nw1, wb, 3) COLGRP(nw1, wc, 2) COLGRP(nw1, wd, 1)
            COLGRP(nw2, wc, 3) COLGRP(nw2, wd, 2)
            COLGRP(nw3, wd, 3)
            #undef COLGRP
            w0v = nw1; w1v = nw2; w2v = nw3;
        }
    }

    // store z[m][ck] as fp16: ck = (lane*4 + c)*3 + k, 12 halves per q
    if (pbase < NLON) {
        const size_t mb = (size_t)(b * NLAT + t) * NLON + pbase;
        #pragma unroll
        for (int q = 0; q < 4; q++) {
            __half2* zp = (__half2*)(g_zh + (mb + q) * (size_t)CK + lane * 12);
            U2F c0k0, c0k1, c0k2, c1k0, c1k1, c1k2;
            c0k0.u = a2[0][q][0]; c0k1.u = a2[1][q][0]; c0k2.u = a2[2][q][0];
            c1k0.u = a2[0][q][1]; c1k1.u = a2[1][q][1]; c1k2.u = a2[2][q][1];
            zp[0] = __floats2half2_rn(c0k0.f.x, c0k1.f.x);
            zp[1] = __floats2half2_rn(c0k2.f.x, c0k0.f.y);
            zp[2] = __floats2half2_rn(c0k1.f.y, c0k2.f.y);
            zp[3] = __floats2half2_rn(c1k0.f.x, c1k1.f.x);
            zp[4] = __floats2half2_rn(c1k2.f.x, c1k0.f.y);
            zp[5] = __floats2half2_rn(c1k1.f.y, c1k2.f.y);
        }
    }
}

// ---------------------------------------------------------------------------
// Stage 2: fp16 mma.sync m16n8k16 GEMM, 4-stage cp.async pipeline.
// SROWB=80 keeps ldmatrix conflict-free (row starts 20r%32 span disjoint
// 4-bank groups) and fits 4 stages in 80KB -> 2 CTAs/SM. Each chunk's loads
// get 2 full iterations of DRAM-latency cover (wait_group<=2).
// ---------------------------------------------------------------------------
__global__ void __launch_bounds__(256, 2)
gemm_mma_kernel(const float* __restrict__ bias, float* __restrict__ out) {
    extern __shared__ __align__(16) char smem[];     // [NSTG][STGB]
    __shared__ float s_bias[COUT];

    const int tid  = threadIdx.x;
    const int warp = tid >> 5;
    const int lane = tid & 31;
    const int g    = lane >> 2;
    const int tg   = lane & 3;
    const int wm   = warp & 3;
    const int wn   = warp >> 2;
    const int m0   = blockIdx.x * MTILE;

    const uint32_t sbase = smem_u32(smem);
    const int lrw = tid >> 1;
    const int lsg = (tid & 1) * 2;

    if (tid < COUT) s_bias[tid] = __ldg(bias + tid);

    const uint32_t lrow = (uint32_t)(lane & 15);
    const uint32_t lsel = (uint32_t)(lane >> 4) * 16;
    uint32_t a_adr[2], b_adr[4];
    #pragma unroll
    for (int mt = 0; mt < 2; mt++)
        a_adr[mt] = sbase + (wm * 32 + mt * 16 + lrow) * SROWB + lsel;
    #pragma unroll
    for (int pr = 0; pr < 4; pr++)
        b_adr[pr] = sbase + CHNKB + (wn * 64 + pr * 16 + lrow) * SROWB + lsel;

    float acc[2][8][4];
    #pragma unroll
    for (int mt = 0; mt < 2; mt++)
        #pragma unroll
        for (int nt = 0; nt < 8; nt++)
            #pragma unroll
            for (int i = 0; i < 4; i++) acc[mt][nt][i] = 0.f;

    #define LOAD_CHUNK(CH, BUFI)                                                   \
    {                                                                              \
        const uint32_t sa = sbase + (uint32_t)(BUFI) * STGB;                       \
        _Pragma("unroll")                                                          \
        for (int s = 0; s < 2; s++) {                                              \
            const int seg = lsg + s;                                               \
            const uint32_t so = (uint32_t)(lrw * SROWB + seg * 16);                \
            cpasync16(sa + so, &g_zh[(size_t)(m0 + lrw) * CK + (CH) * KCH + seg * 8]); \
            cpasync16(sa + CHNKB + so, &g_wh[lrw * CK + (CH) * KCH + seg * 8]);    \
        }                                                                          \
        cp_commit();                                                               \
    }

    LOAD_CHUNK(0, 0)
    LOAD_CHUNK(1, 1)
    LOAD_CHUNK(2, 2)

    for (int ch = 0; ch < NCH; ch++) {
        if (ch + 2 < NCH)      cp_wait<2>();
        else if (ch + 1 < NCH) cp_wait<1>();
        else                   cp_wait<0>();
        __syncthreads();
        if (ch + 3 < NCH) { LOAD_CHUNK(ch + 3, (ch + 3) % NSTG) }

        const uint32_t bufo = (uint32_t)(ch % NSTG) * STGB;
        #pragma unroll
        for (int ksk = 0; ksk < 2; ksk++) {
            const uint32_t ko = bufo + ksk * 32;
            uint32_t afr[2][4];
            #pragma unroll
            for (int mt = 0; mt < 2; mt++)
                ldsm_x4(afr[mt][0], afr[mt][1], afr[mt][2], afr[mt][3],
                        a_adr[mt] + ko);
            #pragma unroll
            for (int pr = 0; pr < 4; pr++) {
                uint32_t r0, r1, r2, r3;
                ldsm_x4(r0, r1, r2, r3, b_adr[pr] + ko);
                mma_f16(acc[0][2 * pr],     afr[0], r0, r2);
                mma_f16(acc[1][2 * pr],     afr[1], r0, r2);
                mma_f16(acc[0][2 * pr + 1], afr[0], r1, r3);
                mma_f16(acc[1][2 * pr + 1], afr[1], r1, r3);
            }
        }
    }

    #pragma unroll
    for (int mt = 0; mt < 2; mt++) {
        const int mlo = m0 + wm * 32 + mt * 16 + g;
        const int mhi = mlo + 8;
        const bool vlo = (mlo < MTOT), vhi = (mhi < MTOT);
        float* plo = nullptr;
        float* phi = nullptr;
        if (vlo) { int bb = mlo / CHW; plo = out + (size_t)bb * COUT * CHW + (mlo - bb * CHW); }
        if (vhi) { int bb = mhi / CHW; phi = out + (size_t)bb * COUT * CHW + (mhi - bb * CHW); }
        #pragma unroll
        for (int nt = 0; nt < 8; nt++) {
            const int f0 = wn * 64 + nt * 8 + tg * 2;
            const float b0 = s_bias[f0], b1 = s_bias[f0 + 1];
            if (vlo) {
                plo[(size_t)f0 * CHW]       = acc[mt][nt][0] + b0;
                plo[(size_t)(f0 + 1) * CHW] = acc[mt][nt][1] + b1;
            }
            if (vhi) {
                phi[(size_t)f0 * CHW]       = acc[mt][nt][2] + b0;
                phi[(size_t)(f0 + 1) * CHW] = acc[mt][nt][3] + b1;
            }
        }
    }
    #undef LOAD_CHUNK
}

// ---------------------------------------------------------------------------
// Launch.
// ---------------------------------------------------------------------------
extern "C" void kernel_launch(void* const* d_in, const int* in_sizes, int n_in,
                              void* d_out, int out_size) {
    const float* x      = (const float*)d_in[0];
    const float* qw     = (const float*)d_in[1];
    const float* vals   = (const float*)d_in[2];
    const float* weight = (const float*)d_in[3];
    const float* bias   = (const float*)d_in[4];
    const int*   seg    = (const int*)d_in[5];
    const int*   lat    = (const int*)d_in[6];
    const int*   lon    = (const int*)d_in[7];
    const int    nnz    = in_sizes[2];

    dim3 tgrid((CHW + 31) / 32, CIN / 32, BSZ);
    transpose_kernel<<<tgrid, dim3(32, 8)>>>(x);
    wconv_kernel<<<(COUT * CK + 255) / 256, 256>>>(weight);
    merge_kernel<<<(NLAT * 32 + 127) / 128, 128>>>(seg, lat, lon, vals, qw, nnz);

    dim3 ggrid(NPT, NLAT, BSZ);
    gather_kernel<<<ggrid, 256>>>();

    const int dyn_bytes = NSTG * STGB;   // 81920
    cudaFuncSetAttribute(gemm_mma_kernel,
                         cudaFuncAttributeMaxDynamicSharedMemorySize, dyn_bytes);
    gemm_mma_kernel<<<MBLK, 256, dyn_bytes>>>(bias, (float*)d_out);
}

// round 14
// speedup vs baseline: 1.1263x; 1.0182x over previous
#include <cuda_runtime.h>
#include <cuda_fp16.h>
#include <cstdint>

// Problem constants
#define NLAT 181
#define NLON 360
#define CIN  128
#define COUT 128
#define KS   3
#define BSZ  2
#define CHW  (NLAT * NLON)     // 65160
#define CK   (CIN * KS)        // 384
#define PT   32                // gather p-tile
#define NPT  12
#define MTOT  (BSZ * CHW)      // 130320
#define MTILE 128
#define MBLK  ((MTOT + MTILE - 1) / MTILE)   // 1019
#define MPADL (MBLK * MTILE)                 // 130432
#define WSLOT 4096
#define RSLOT 1024             // more runs after segment splitting
#define KCH   32               // GEMM K-chunk (halves)
#define NCH   (CK / KCH)       // 12
#define SROWB 80               // smem row stride bytes (conflict-free)
#define CHNKB (128 * SROWB)    // 10240
#define STGB  (2 * CHNKB)      // 20480 per stage (A+B)
#define NSTG  4

// Scratch (device globals — allocation-free; zero-init so padded z rows are 0)
__device__ float  g_xt[(size_t)BSZ * CHW * CIN];   // x transposed: [b][h*w][c]
__device__ float2 g_rw2[NLAT * WSLOT];             // per-entry {w_lo, w_hi}
__device__ int4   g_runs[NLAT * RSLOT];            // {la|(s<<16), lo0, cnt_pad, wabs}
__device__ int    g_rcnt[NLAT];
__device__ __half g_zh[(size_t)MPADL * CK];        // z M-major [m][ck], fp16
__device__ __half g_wh[COUT * CK];                 // W [f][ck], fp16

// ---------------- helpers ----------------
__device__ __forceinline__ void fma2(unsigned long long& d,
                                     unsigned long long a,
                                     unsigned long long b) {
    asm("fma.rn.f32x2 %0, %1, %2, %0;" : "+l"(d) : "l"(a), "l"(b));
}
__device__ __forceinline__ unsigned long long pack2(float x, float y) {
    unsigned long long r;
    asm("mov.b64 %0, {%1, %2};" : "=l"(r) : "f"(x), "f"(y));
    return r;
}
union F4U { float4 f; unsigned long long u[2]; };
union U2F { unsigned long long u; float2 f; };

__device__ __forceinline__ uint32_t smem_u32(const void* p) {
    uint32_t a;
    asm("{ .reg .u64 t; cvta.to.shared.u64 t, %1; cvt.u32.u64 %0, t; }"
        : "=r"(a) : "l"(p));
    return a;
}
__device__ __forceinline__ void cpasync16(uint32_t s, const void* g) {
    asm volatile("cp.async.cg.shared.global [%0], [%1], 16;" :: "r"(s), "l"(g));
}
__device__ __forceinline__ void cp_commit() {
    asm volatile("cp.async.commit_group;" ::: "memory");
}
template <int N>
__device__ __forceinline__ void cp_wait() {
    asm volatile("cp.async.wait_group %0;" :: "n"(N) : "memory");
}
__device__ __forceinline__ void mma_f16(float* d, const uint32_t* a,
                                        uint32_t b0, uint32_t b1) {
    asm volatile(
        "mma.sync.aligned.m16n8k16.row.col.f32.f16.f16.f32 "
        "{%0,%1,%2,%3}, {%4,%5,%6,%7}, {%8,%9}, {%0,%1,%2,%3};"
        : "+f"(d[0]), "+f"(d[1]), "+f"(d[2]), "+f"(d[3])
        : "r"(a[0]), "r"(a[1]), "r"(a[2]), "r"(a[3]), "r"(b0), "r"(b1));
}
__device__ __forceinline__ void ldsm_x4(uint32_t& r0, uint32_t& r1,
                                        uint32_t& r2, uint32_t& r3, uint32_t addr) {
    asm volatile("ldmatrix.sync.aligned.m8n8.x4.shared.b16 {%0,%1,%2,%3}, [%4];"
                 : "=r"(r0), "=r"(r1), "=r"(r2), "=r"(r3) : "r"(addr));
}

// ---------------------------------------------------------------------------
// Transpose x[b][c][hw] -> g_xt[b][hw][c]
// ---------------------------------------------------------------------------
__global__ void transpose_kernel(const float* __restrict__ x) {
    __shared__ float tile[32][33];
    const int hw0 = blockIdx.x * 32;
    const int c0  = blockIdx.y * 32;
    const int b   = blockIdx.z;
    const int tx = threadIdx.x, ty = threadIdx.y;
    #pragma unroll
    for (int i = 0; i < 4; i++) {
        int c  = c0 + ty + i * 8;
        int hw = hw0 + tx;
        if (hw < CHW)
            tile[ty + i * 8][tx] = x[((size_t)b * CIN + c) * CHW + hw];
    }
    __syncthreads();
    #pragma unroll
    for (int i = 0; i < 4; i++) {
        int hw = hw0 + ty + i * 8;
        int c  = c0 + tx;
        if (hw < CHW)
            g_xt[((size_t)b * CHW + hw) * CIN + c] = tile[tx][ty + i * 8];
    }
}

// W[f][ck] -> fp16 copy
__global__ void wconv_kernel(const float* __restrict__ w) {
    int i = blockIdx.x * 256 + threadIdx.x;
    if (i < COUT * CK) g_wh[i] = __float2half_rn(w[i]);
}

// ---------------------------------------------------------------------------
// Merge: warp per t. Each ψ-point lies in one hat segment s (only hats s and
// s+1 nonzero; s=2 has a single weight). Emit runs of consecutive lons with
// UNIFORM s, weights as {w_lo, w_hi}, zero-padded to multiples of 4.
// ---------------------------------------------------------------------------
__global__ void merge_kernel(const int* __restrict__ seg,
                             const int* __restrict__ lat,
                             const int* __restrict__ lon,
                             const float* __restrict__ vals,
                             const float* __restrict__ qw,
                             int nnz) {
    const int t    = (blockIdx.x * blockDim.x + threadIdx.x) >> 5;
    const int lane = threadIdx.x & 31;
    if (t >= NLAT) return;

    int sb[4];
    #pragma unroll
    for (int k = 0; k < 4; k++) {
        const int j = t * KS + k;
        int lo = 0, hi = nnz;
        while (lo < hi) {
            int m = (lo + hi) >> 1;
            int sgv = seg[m];
            int key = (sgv % NLAT) * KS + (sgv / NLAT);
            if (key < j) lo = m + 1; else hi = m;
        }
        sb[k] = lo;
    }

    const int wlim = (t + 1) * WSLOT;
    int wabs = 0, rbase = 0;
    int entc = 0, runsc = 0;

    for (int pass = 0; pass < 2; pass++) {
        int ent = 0, runs = 0;
        for (int la = lane; la < NLAT; la += 32) {
            int bks[3], eks[3];
            #pragma unroll
            for (int k = 0; k < 3; k++) {
                int lo = sb[k], hi = sb[k + 1];
                while (lo < hi) { int m = (lo + hi) >> 1; if (lat[m] < la) lo = m + 1; else hi = m; }
                bks[k] = lo;
                hi = sb[k + 1];
                while (lo < hi) { int m = (lo + hi) >> 1; if (lat[m] < la + 1) lo = m + 1; else hi = m; }
                eks[k] = lo;
            }
            int p0 = bks[0], p1 = bks[1], p2 = bks[2];
            const float q = qw[la];
            int prev = -2, prevs = -1, rstart = ent, rcnt = 0, rlo0 = 0;
            while (p0 < eks[0] || p1 < eks[1] || p2 < eks[2]) {
                int l0 = (p0 < eks[0]) ? lon[p0] : 0x7fffffff;
                int l1 = (p1 < eks[1]) ? lon[p1] : 0x7fffffff;
                int l2 = (p2 < eks[2]) ? lon[p2] : 0x7fffffff;
                int lm = min(l0, min(l1, l2));
                float w0 = 0.f, w1 = 0.f, w2 = 0.f;
                if (l0 == lm) { w0 = vals[p0] * q; p0++; }
                if (l1 == lm) { w1 = vals[p1] * q; p1++; }
                if (l2 == lm) { w2 = vals[p2] * q; p2++; }
                if (w0 == 0.f && w1 == 0.f && w2 == 0.f) continue;
                // segment classification (w0 and w2 are mutually exclusive)
                int s; float wl, wh;
                if      (w0 != 0.f) { s = 0; wl = w0; wh = w1; }
                else if (w1 != 0.f) { s = 1; wl = w1; wh = w2; }
                else                { s = 2; wl = w2; wh = 0.f; }
                if (rcnt > 0 && (lm != prev + 1 || s != prevs)) {
                    int pad = (4 - (rcnt & 3)) & 3;
                    if (pass == 1) {
                        for (int z = 0; z < pad; z++) {
                            int ai = wabs + rstart + rcnt + z;
                            if (ai < wlim) g_rw2[ai] = make_float2(0.f, 0.f);
                        }
                        int ri = rbase + runs;
                        if (ri < RSLOT)
                            g_runs[t * RSLOT + ri] =
                                make_int4((prevs << 16) | la, rlo0,
                                          rcnt + pad, wabs + rstart);
                    }
                    runs++;
                    ent = rstart + rcnt + pad;
                    rstart = ent; rcnt = 0;
                }
                if (rcnt == 0) rlo0 = lm;
                if (pass == 1) {
                    int ai = wabs + rstart + rcnt;
                    if (ai < wlim) g_rw2[ai] = make_float2(wl, wh);
                }
                rcnt++;
                ent = rstart + rcnt;
                prev = lm;
                prevs = s;
            }
            if (rcnt > 0) {
                int pad = (4 - (rcnt & 3)) & 3;
                if (pass == 1) {
                    for (int z = 0; z < pad; z++) {
                        int ai = wabs + rstart + rcnt + z;
                        if (ai < wlim) g_rw2[ai] = make_float2(0.f, 0.f);
                    }
                    int ri = rbase + runs;
                    if (ri < RSLOT)
                        g_runs[t * RSLOT + ri] =
                            make_int4((prevs << 16) | la, rlo0,
                                      rcnt + pad, wabs + rstart);
                }
                runs++;
                ent = rstart + rcnt + pad;
            }
        }
        if (pass == 0) {
            entc = ent; runsc = runs;
            int ei = entc, ri = runsc;
            #pragma unroll
            for (int d = 1; d < 32; d <<= 1) {
                int v = __shfl_up_sync(0xffffffffu, ei, d);
                int u = __shfl_up_sync(0xffffffffu, ri, d);
                if (lane >= d) { ei += v; ri += u; }
            }
            wabs  = t * WSLOT + (ei - entc);
            rbase = ri - runsc;
            if (lane == 31) g_rcnt[t] = min(ri, RSLOT);
        }
    }
}

// ---------------------------------------------------------------------------
// Stage 1: gather. Per run, warp-uniform dispatch on segment s: 2 fma2 per
// entry-column for s<2, 1 for s=2 (was always 3). Rolling column window,
// column-ordered fma for load-latency cover. Writes z fp16 M-major.
// ---------------------------------------------------------------------------
__global__ void __launch_bounds__(256, 2)
gather_kernel() {
    const int tid  = threadIdx.x;
    const int warp = tid >> 5;
    const int lane = tid & 31;

    const int yb = blockIdx.y;
    const int t  = (yb & 1) ? (NLAT - 1 - (yb >> 1)) : (yb >> 1);   // pole-first
    const int b  = blockIdx.z;
    const int p0 = blockIdx.x * PT;
    const int pbase = p0 + warp * 4;

    const int nruns = g_rcnt[t];
    const int4* runs = g_runs + (size_t)t * RSLOT;
    const float4* xb = (const float4*)(g_xt + (size_t)b * CHW * CIN);

    unsigned long long a2[3][4][2];
    #pragma unroll
    for (int k = 0; k < 3; k++)
        #pragma unroll
        for (int q = 0; q < 4; q++) { a2[k][q][0] = 0ull; a2[k][q][1] = 0ull; }

    for (int r = 0; r < nruns; r++) {
        const int4 rn = __ldg(&runs[r]);
        const int la   = rn.x & 0xffff;
        const int s    = rn.x >> 16;
        const int cnt  = rn.z;                 // multiple of 4
        const float4* wp = (const float4*)(g_rw2 + rn.w);
        const int rowb = la * NLON;

        int col = rn.y + pbase;
        if (col >= NLON) col -= NLON;
        if (col >= NLON) col -= NLON;
        int c1 = col + 1; if (c1 >= NLON) c1 -= NLON;
        int c2 = c1 + 1;  if (c2 >= NLON) c2 -= NLON;

        F4U w0v, w1v, w2v;
        w0v.f = xb[(size_t)(rowb + col) * 32 + lane];
        w1v.f = xb[(size_t)(rowb + c1)  * 32 + lane];
        w2v.f = xb[(size_t)(rowb + c2)  * 32 + lane];
        int colx = c2;

        // per (column V, entry weight pair (WL,WH), acc lane Q): 4 fma2
        #define CG2(V, WL, WH, KA, KB, Q)                                         \
        {                                                                         \
            unsigned long long kk;                                                \
            kk = pack2(WL, WL);                                                   \
            fma2(a2[KA][Q][0], kk, V.u[0]); fma2(a2[KA][Q][1], kk, V.u[1]);       \
            kk = pack2(WH, WH);                                                   \
            fma2(a2[KB][Q][0], kk, V.u[0]); fma2(a2[KB][Q][1], kk, V.u[1]);       \
        }
        #define CG1(V, WL, KA, Q)                                                 \
        {                                                                         \
            unsigned long long kk = pack2(WL, WL);                                \
            fma2(a2[KA][Q][0], kk, V.u[0]); fma2(a2[KA][Q][1], kk, V.u[1]);       \
        }
        // entry weights: a=(fa.x,fa.y) b=(fa.z,fa.w) c=(fb.x,fb.y) d=(fb.z,fb.w)
        #define RUN_LOOP2(KA, KB)                                                 \
        for (int j4 = 0; j4 < cnt; j4 += 4) {                                     \
            int n0 = colx + 1; if (n0 >= NLON) n0 -= NLON;                        \
            int n1 = colx + 2; if (n1 >= NLON) n1 -= NLON;                        \
            int n2 = colx + 3; if (n2 >= NLON) n2 -= NLON;                        \
            int n3 = colx + 4; if (n3 >= NLON) n3 -= NLON;                        \
            colx = n3;                                                            \
            F4U nw0, nw1, nw2, nw3;                                               \
            nw0.f = xb[(size_t)(rowb + n0) * 32 + lane];                          \
            nw1.f = xb[(size_t)(rowb + n1) * 32 + lane];                          \
            nw2.f = xb[(size_t)(rowb + n2) * 32 + lane];                          \
            nw3.f = xb[(size_t)(rowb + n3) * 32 + lane];                          \
            float4 fa = __ldg(&wp[j4 >> 1]);                                      \
            float4 fb = __ldg(&wp[(j4 >> 1) + 1]);                                \
            CG2(w0v, fa.x, fa.y, KA, KB, 0)                                       \
            CG2(w1v, fa.x, fa.y, KA, KB, 1) CG2(w1v, fa.z, fa.w, KA, KB, 0)       \
            CG2(w2v, fa.x, fa.y, KA, KB, 2) CG2(w2v, fa.z, fa.w, KA, KB, 1)       \
            CG2(w2v, fb.x, fb.y, KA, KB, 0)                                       \
            CG2(nw0, fa.x, fa.y, KA, KB, 3) CG2(nw0, fa.z, fa.w, KA, KB, 2)       \
            CG2(nw0, fb.x, fb.y, KA, KB, 1) CG2(nw0, fb.z, fb.w, KA, KB, 0)       \
            CG2(nw1, fa.z, fa.w, KA, KB, 3) CG2(nw1, fb.x, fb.y, KA, KB, 2)       \
            CG2(nw1, fb.z, fb.w, KA, KB, 1)                                       \
            CG2(nw2, fb.x, fb.y, KA, KB, 3) CG2(nw2, fb.z, fb.w, KA, KB, 2)       \
            CG2(nw3, fb.z, fb.w, KA, KB, 3)                                       \
            w0v = nw1; w1v = nw2; w2v = nw3;                                      \
        }
        #define RUN_LOOP1(KA)                                                     \
        for (int j4 = 0; j4 < cnt; j4 += 4) {                                     \
            int n0 = colx + 1; if (n0 >= NLON) n0 -= NLON;                        \
            int n1 = colx + 2; if (n1 >= NLON) n1 -= NLON;                        \
            int n2 = colx + 3; if (n2 >= NLON) n2 -= NLON;                        \
            int n3 = colx + 4; if (n3 >= NLON) n3 -= NLON;                        \
            colx = n3;                                                            \
            F4U nw0, nw1, nw2, nw3;                                               \
            nw0.f = xb[(size_t)(rowb + n0) * 32 + lane];                          \
            nw1.f = xb[(size_t)(rowb + n1) * 32 + lane];                          \
            nw2.f = xb[(size_t)(rowb + n2) * 32 + lane];                          \
            nw3.f = xb[(size_t)(rowb + n3) * 32 + lane];                          \
            float4 fa = __ldg(&wp[j4 >> 1]);                                      \
            float4 fb = __ldg(&wp[(j4 >> 1) + 1]);                                \
            CG1(w0v, fa.x, KA, 0)                                                 \
            CG1(w1v, fa.x, KA, 1) CG1(w1v, fa.z, KA, 0)                           \
            CG1(w2v, fa.x, KA, 2) CG1(w2v, fa.z, KA, 1) CG1(w2v, fb.x, KA, 0)     \
            CG1(nw0, fa.x, KA, 3) CG1(nw0, fa.z, KA, 2) CG1(nw0, fb.x, KA, 1)     \
            CG1(nw0, fb.z, KA, 0)                                                 \
            CG1(nw1, fa.z, KA, 3) CG1(nw1, fb.x, KA, 2) CG1(nw1, fb.z, KA, 1)     \
            CG1(nw2, fb.x, KA, 3) CG1(nw2, fb.z, KA, 2)                           \
            CG1(nw3, fb.z, KA, 3)                                                 \
            w0v = nw1; w1v = nw2; w2v = nw3;                                      \
        }

        if (s == 0)      { RUN_LOOP2(0, 1) }
        else if (s == 1) { RUN_LOOP2(1, 2) }
        else             { RUN_LOOP1(2) }

        #undef RUN_LOOP2
        #undef RUN_LOOP1
        #undef CG2
        #undef CG1
    }

    // store z[m][ck] as fp16: ck = (lane*4 + c)*3 + k, 12 halves per q
    if (pbase < NLON) {
        const size_t mb = (size_t)(b * NLAT + t) * NLON + pbase;
        #pragma unroll
        for (int q = 0; q < 4; q++) {
            __half2* zp = (__half2*)(g_zh + (mb + q) * (size_t)CK + lane * 12);
            U2F c0k0, c0k1, c0k2, c1k0, c1k1, c1k2;
            c0k0.u = a2[0][q][0]; c0k1.u = a2[1][q][0]; c0k2.u = a2[2][q][0];
            c1k0.u = a2[0][q][1]; c1k1.u = a2[1][q][1]; c1k2.u = a2[2][q][1];
            zp[0] = __floats2half2_rn(c0k0.f.x, c0k1.f.x);
            zp[1] = __floats2half2_rn(c0k2.f.x, c0k0.f.y);
            zp[2] = __floats2half2_rn(c0k1.f.y, c0k2.f.y);
            zp[3] = __floats2half2_rn(c1k0.f.x, c1k1.f.x);
            zp[4] = __floats2half2_rn(c1k2.f.x, c1k0.f.y);
            zp[5] = __floats2half2_rn(c1k1.f.y, c1k2.f.y);
        }
    }
}

// ---------------------------------------------------------------------------
// Stage 2: fp16 mma.sync m16n8k16 GEMM, 4-stage cp.async pipeline (R13).
// ---------------------------------------------------------------------------
__global__ void __launch_bounds__(256, 2)
gemm_mma_kernel(const float* __restrict__ bias, float* __restrict__ out) {
    extern __shared__ __align__(16) char smem[];     // [NSTG][STGB]
    __shared__ float s_bias[COUT];

    const int tid  = threadIdx.x;
    const int warp = tid >> 5;
    const int lane = tid & 31;
    const int g    = lane >> 2;
    const int tg   = lane & 3;
    const int wm   = warp & 3;
    const int wn   = warp >> 2;
    const int m0   = blockIdx.x * MTILE;

    const uint32_t sbase = smem_u32(smem);
    const int lrw = tid >> 1;
    const int lsg = (tid & 1) * 2;

    if (tid < COUT) s_bias[tid] = __ldg(bias + tid);

    const uint32_t lrow = (uint32_t)(lane & 15);
    const uint32_t lsel = (uint32_t)(lane >> 4) * 16;
    uint32_t a_adr[2], b_adr[4];
    #pragma unroll
    for (int mt = 0; mt < 2; mt++)
        a_adr[mt] = sbase + (wm * 32 + mt * 16 + lrow) * SROWB + lsel;
    #pragma unroll
    for (int pr = 0; pr < 4; pr++)
        b_adr[pr] = sbase + CHNKB + (wn * 64 + pr * 16 + lrow) * SROWB + lsel;

    float acc[2][8][4];
    #pragma unroll
    for (int mt = 0; mt < 2; mt++)
        #pragma unroll
        for (int nt = 0; nt < 8; nt++)
            #pragma unroll
            for (int i = 0; i < 4; i++) acc[mt][nt][i] = 0.f;

    #define LOAD_CHUNK(CH, BUFI)                                                   \
    {                                                                              \
        const uint32_t sa = sbase + (uint32_t)(BUFI) * STGB;                       \
        _Pragma("unroll")                                                          \
        for (int s = 0; s < 2; s++) {                                              \
            const int seg = lsg + s;                                               \
            const uint32_t so = (uint32_t)(lrw * SROWB + seg * 16);                \
            cpasync16(sa + so, &g_zh[(size_t)(m0 + lrw) * CK + (CH) * KCH + seg * 8]); \
            cpasync16(sa + CHNKB + so, &g_wh[lrw * CK + (CH) * KCH + seg * 8]);    \
        }                                                                          \
        cp_commit();                                                               \
    }

    LOAD_CHUNK(0, 0)
    LOAD_CHUNK(1, 1)
    LOAD_CHUNK(2, 2)

    for (int ch = 0; ch < NCH; ch++) {
        if (ch + 2 < NCH)      cp_wait<2>();
        else if (ch + 1 < NCH) cp_wait<1>();
        else                   cp_wait<0>();
        __syncthreads();
        if (ch + 3 < NCH) { LOAD_CHUNK(ch + 3, (ch + 3) % NSTG) }

        const uint32_t bufo = (uint32_t)(ch % NSTG) * STGB;
        #pragma unroll
        for (int ksk = 0; ksk < 2; ksk++) {
            const uint32_t ko = bufo + ksk * 32;
            uint32_t afr[2][4];
            #pragma unroll
            for (int mt = 0; mt < 2; mt++)
                ldsm_x4(afr[mt][0], afr[mt][1], afr[mt][2], afr[mt][3],
                        a_adr[mt] + ko);
            #pragma unroll
            for (int pr = 0; pr < 4; pr++) {
                uint32_t r0, r1, r2, r3;
                ldsm_x4(r0, r1, r2, r3, b_adr[pr] + ko);
                mma_f16(acc[0][2 * pr],     afr[0], r0, r2);
                mma_f16(acc[1][2 * pr],     afr[1], r0, r2);
                mma_f16(acc[0][2 * pr + 1], afr[0], r1, r3);
                mma_f16(acc[1][2 * pr + 1], afr[1], r1, r3);
            }
        }
    }

    #pragma unroll
    for (int mt = 0; mt < 2; mt++) {
        const int mlo = m0 + wm * 32 + mt * 16 + g;
        const int mhi = mlo + 8;
        const bool vlo = (mlo < MTOT), vhi = (mhi < MTOT);
        float* plo = nullptr;
        float* phi = nullptr;
        if (vlo) { int bb = mlo / CHW; plo = out + (size_t)bb * COUT * CHW + (mlo - bb * CHW); }
        if (vhi) { int bb = mhi / CHW; phi = out + (size_t)bb * COUT * CHW + (mhi - bb * CHW); }
        #pragma unroll
        for (int nt = 0; nt < 8; nt++) {
            const int f0 = wn * 64 + nt * 8 + tg * 2;
            const float b0 = s_bias[f0], b1 = s_bias[f0 + 1];
            if (vlo) {
                plo[(size_t)f0 * CHW]       = acc[mt][nt][0] + b0;
                plo[(size_t)(f0 + 1) * CHW] = acc[mt][nt][1] + b1;
            }
            if (vhi) {
                phi[(size_t)f0 * CHW]       = acc[mt][nt][2] + b0;
                phi[(size_t)(f0 + 1) * CHW] = acc[mt][nt][3] + b1;
            }
        }
    }
    #undef LOAD_CHUNK
}

// ---------------------------------------------------------------------------
// Launch.
// ---------------------------------------------------------------------------
extern "C" void kernel_launch(void* const* d_in, const int* in_sizes, int n_in,
                              void* d_out, int out_size) {
    const float* x      = (const float*)d_in[0];
    const float* qw     = (const float*)d_in[1];
    const float* vals   = (const float*)d_in[2];
    const float* weight = (const float*)d_in[3];
    const float* bias   = (const float*)d_in[4];
    const int*   seg    = (const int*)d_in[5];
    const int*   lat    = (const int*)d_in[6];
    const int*   lon    = (const int*)d_in[7];
    const int    nnz    = in_sizes[2];

    dim3 tgrid((CHW + 31) / 32, CIN / 32, BSZ);
    transpose_kernel<<<tgrid, dim3(32, 8)>>>(x);
    wconv_kernel<<<(COUT * CK + 255) / 256, 256>>>(weight);
    merge_kernel<<<(NLAT * 32 + 127) / 128, 128>>>(seg, lat, lon, vals, qw, nnz);

    dim3 ggrid(NPT, NLAT, BSZ);
    gather_kernel<<<ggrid, 256>>>();

    const int dyn_bytes = NSTG * STGB;   // 81920
    cudaFuncSetAttribute(gemm_mma_kernel,
                         cudaFuncAttributeMaxDynamicSharedMemorySize, dyn_bytes);
    gemm_mma_kernel<<<MBLK, 256, dyn_bytes>>>(bias, (float*)d_out);
}